// round 3
// baseline (speedup 1.0000x reference)
#include <cuda_runtime.h>

// ---------------------------------------------------------------------------
// 2-layer GAT (heads=2). Layer1: in=64 -> out_ch=64 (FT=128). Layer2: in=128
// -> out_ch=128 (FT=256). Segment softmax over (edges + self loops).
// Strategy: accumulate unnormalized exp-weighted messages, divide by segment
// denominator at the end. All scratch lives in __device__ globals referenced
// directly by the kernels (no host-side symbol lookups, no allocations).
// ---------------------------------------------------------------------------

#define NN 50000

__device__ float g_xl1[NN * 128];
__device__ float g_out1[NN * 128];   // layer1 accumulator, then normalized h
__device__ float g_xl2[NN * 256];
__device__ float g_asrc[NN * 2];
__device__ float g_adst[NN * 2];
__device__ float g_m[NN * 2];
__device__ float g_denom[NN * 2];

__device__ __forceinline__ float leaky(float a) { return a > 0.f ? a : 0.2f * a; }

__device__ __forceinline__ void red_add_v2(float* addr, float x, float y) {
    asm volatile("red.global.add.v2.f32 [%0], {%1,%2};"
                 :: "l"(addr), "f"(x), "f"(y) : "memory");
}
__device__ __forceinline__ void red_add_v4(float4* addr, float x, float y, float z, float w) {
    asm volatile("red.global.add.v4.f32 [%0], {%1,%2,%3,%4};"
                 :: "l"(addr), "f"(x), "f"(y), "f"(z), "f"(w) : "memory");
}
__device__ __forceinline__ void atomic_max_float(float* addr, float v) {
    if (v >= 0.f) atomicMax((int*)addr, __float_as_int(v));
    else          atomicMin((unsigned int*)addr, __float_as_uint(v));
}

// ---------------------------------------------------------------------------
// GEMM: C[M,NC] = A[M,KTOT] @ B[KTOT,NC].  TILE_M=64, BK=32, 256 threads.
// Thread (ty,tx): rows ty*8+i (i<8), cols tx+32*j (j<NC/32).
// ---------------------------------------------------------------------------
template <int KTOT, int NC>
__global__ __launch_bounds__(256)
void gemm_kernel(const float* __restrict__ A, const float* __restrict__ B,
                 float* __restrict__ C, int M)
{
    constexpr int TM = 64, BK = 32;
    constexpr int RM = 8;
    constexpr int RN = NC / 32;

    __shared__ float sA[BK][TM + 1];
    __shared__ float sB[BK][NC];

    const int tid = threadIdx.x;
    const int tx = tid & 31, ty = tid >> 5;
    const int m0 = blockIdx.x * TM;

    float acc[RM][RN];
#pragma unroll
    for (int i = 0; i < RM; i++)
#pragma unroll
        for (int j = 0; j < RN; j++) acc[i][j] = 0.f;

    for (int k0 = 0; k0 < KTOT; k0 += BK) {
        // load A tile (64 x 32)
#pragma unroll
        for (int i = 0; i < (TM * BK) / 256; i++) {
            int idx = tid + 256 * i;
            int r = idx >> 5;
            int kk = idx & 31;
            int row = m0 + r;
            sA[kk][r] = (row < M) ? A[(size_t)row * KTOT + k0 + kk] : 0.f;
        }
        // load B tile (32 x NC)
#pragma unroll
        for (int i = 0; i < (BK * NC) / 256; i++) {
            int idx = tid + 256 * i;
            int kk = idx / NC;
            int c  = idx % NC;
            sB[kk][c] = B[(size_t)(k0 + kk) * NC + c];
        }
        __syncthreads();

#pragma unroll 4
        for (int kk = 0; kk < BK; kk++) {
            float xv[RM], wv[RN];
#pragma unroll
            for (int i = 0; i < RM; i++) xv[i] = sA[kk][ty * RM + i];
#pragma unroll
            for (int j = 0; j < RN; j++) wv[j] = sB[kk][tx + 32 * j];
#pragma unroll
            for (int i = 0; i < RM; i++)
#pragma unroll
                for (int j = 0; j < RN; j++) acc[i][j] += xv[i] * wv[j];
        }
        __syncthreads();
    }

#pragma unroll
    for (int i = 0; i < RM; i++) {
        int row = m0 + ty * RM + i;
        if (row < M) {
#pragma unroll
            for (int j = 0; j < RN; j++)
                C[(size_t)row * NC + tx + 32 * j] = acc[i][j];
        }
    }
}

// ---------------------------------------------------------------------------
// Attention coefficients: a_src[n,h] = dot(xl[n,h,:], att_src[h,:]).
// One warp per node. att arrays are [H,F] flat = same layout as an xl row.
// ---------------------------------------------------------------------------
template <int F>
__global__ void attn_kernel(const float* __restrict__ xl,
                            const float* __restrict__ att_s,
                            const float* __restrict__ att_d,
                            int n_nodes)
{
    constexpr int FT = 2 * F;
    int w = (blockIdx.x * blockDim.x + threadIdx.x) >> 5;
    int lane = threadIdx.x & 31;
    if (w >= n_nodes) return;

    const float4* row = (const float4*)(xl + (size_t)w * FT);
    const float4* as4 = (const float4*)att_s;
    const float4* ad4 = (const float4*)att_d;

    if constexpr (F == 64) {
        float4 v = row[lane], a = as4[lane], b = ad4[lane];
        float ps = v.x * a.x + v.y * a.y + v.z * a.z + v.w * a.w;
        float pd = v.x * b.x + v.y * b.y + v.z * b.z + v.w * b.w;
#pragma unroll
        for (int o = 8; o > 0; o >>= 1) {
            ps += __shfl_xor_sync(0xffffffffu, ps, o);
            pd += __shfl_xor_sync(0xffffffffu, pd, o);
        }
        if (lane == 0)  { g_asrc[2 * w]     = ps; g_adst[2 * w]     = pd; }
        if (lane == 16) { g_asrc[2 * w + 1] = ps; g_adst[2 * w + 1] = pd; }
    } else {
        // F == 128: lane covers float4 j=lane (head0) and j=lane+32 (head1)
        float4 v0 = row[lane],      a0 = as4[lane],      b0 = ad4[lane];
        float4 v1 = row[lane + 32], a1 = as4[lane + 32], b1 = ad4[lane + 32];
        float ps0 = v0.x * a0.x + v0.y * a0.y + v0.z * a0.z + v0.w * a0.w;
        float pd0 = v0.x * b0.x + v0.y * b0.y + v0.z * b0.z + v0.w * b0.w;
        float ps1 = v1.x * a1.x + v1.y * a1.y + v1.z * a1.z + v1.w * a1.w;
        float pd1 = v1.x * b1.x + v1.y * b1.y + v1.z * b1.z + v1.w * b1.w;
#pragma unroll
        for (int o = 16; o > 0; o >>= 1) {
            ps0 += __shfl_xor_sync(0xffffffffu, ps0, o);
            pd0 += __shfl_xor_sync(0xffffffffu, pd0, o);
            ps1 += __shfl_xor_sync(0xffffffffu, ps1, o);
            pd1 += __shfl_xor_sync(0xffffffffu, pd1, o);
        }
        if (lane == 0) {
            g_asrc[2 * w] = ps0; g_asrc[2 * w + 1] = ps1;
            g_adst[2 * w] = pd0; g_adst[2 * w + 1] = pd1;
        }
    }
}

// Initialize m with the self-loop alpha (every node has exactly one self loop).
__global__ void init_max_kernel(int n2)
{
    int i = blockIdx.x * blockDim.x + threadIdx.x;
    if (i < n2) g_m[i] = leaky(g_asrc[i] + g_adst[i]);
}

// Segment max over real edges (atomic).
__global__ void edge_max_kernel(const int* __restrict__ src, const int* __restrict__ dst,
                                int ne)
{
    int i = blockIdx.x * blockDim.x + threadIdx.x;
    if (i >= ne) return;
    int s = src[i], d = dst[i];
#pragma unroll
    for (int h = 0; h < 2; h++) {
        float a = leaky(g_asrc[2 * s + h] + g_adst[2 * d + h]);
        atomic_max_float(&g_m[2 * d + h], a);
    }
}

// Initialize out with self-loop message and denom with self-loop weight.
template <int F>
__global__ void node_init_kernel(const float* __restrict__ xl, float* __restrict__ out,
                                 int n_nodes)
{
    constexpr int FT = 2 * F;
    long long i = (long long)blockIdx.x * blockDim.x + threadIdx.x;
    if (i >= (long long)n_nodes * FT) return;
    int n = (int)(i / FT), f = (int)(i % FT);
    int h = f / F;
    float a = leaky(g_asrc[2 * n + h] + g_adst[2 * n + h]);
    float e = __expf(a - g_m[2 * n + h]);
    out[i] = e * xl[i];
    if (f == h * F) g_denom[2 * n + h] = e;
}

// Warp-per-edge: accumulate exp-weighted source features into destination rows.
template <int F>
__global__ void edge_accum_kernel(const int* __restrict__ src, const int* __restrict__ dst,
                                  const float* __restrict__ xl, float* __restrict__ out,
                                  int ne)
{
    constexpr int FT = 2 * F, NV = FT / 4;
    long long t = (long long)blockIdx.x * blockDim.x + threadIdx.x;
    int w = (int)(t >> 5);
    int lane = threadIdx.x & 31;
    if (w >= ne) return;
    int s = src[w], d = dst[w];

    float a0 = leaky(g_asrc[2 * s]     + g_adst[2 * d]);
    float a1 = leaky(g_asrc[2 * s + 1] + g_adst[2 * d + 1]);
    float e0 = __expf(a0 - g_m[2 * d]);
    float e1 = __expf(a1 - g_m[2 * d + 1]);
    if (lane == 0) red_add_v2(&g_denom[2 * d], e0, e1);

    const float4* xs = (const float4*)(xl + (size_t)s * FT);
    float4* od = (float4*)(out + (size_t)d * FT);
#pragma unroll
    for (int q = 0; q < NV / 32; q++) {
        int j = lane + 32 * q;
        float e = (j * 4 < F) ? e0 : e1;
        float4 v = xs[j];
        red_add_v4(od + j, v.x * e, v.y * e, v.z * e, v.w * e);
    }
}

// Final: divide by denominator, add bias.
template <int F>
__global__ void normalize_kernel(float* __restrict__ out, const float* __restrict__ bias,
                                 int n_nodes)
{
    constexpr int FT = 2 * F;
    long long i = (long long)blockIdx.x * blockDim.x + threadIdx.x;
    if (i >= (long long)n_nodes * FT) return;
    int n = (int)(i / FT), f = (int)(i % FT);
    int h = f / F;
    out[i] = out[i] / g_denom[2 * n + h] + bias[f];
}

// ---------------------------------------------------------------------------

extern "C" void kernel_launch(void* const* d_in, const int* in_sizes, int n_in,
                              void* d_out, int out_size)
{
    const float* x   = (const float*)d_in[0];
    const int*   und = (const int*)d_in[1];
    const int*   dir = (const int*)d_in[2];
    const float* W1  = (const float*)d_in[3];
    const float* as1 = (const float*)d_in[4];
    const float* ad1 = (const float*)d_in[5];
    const float* b1  = (const float*)d_in[6];
    const float* W2  = (const float*)d_in[7];
    const float* as2 = (const float*)d_in[8];
    const float* ad2 = (const float*)d_in[9];
    const float* b2  = (const float*)d_in[10];
    float* out = (float*)d_out;

    const int n  = in_sizes[0] / 64;   // 50000
    const int e1 = in_sizes[1] / 2;    // 800000
    const int e2 = in_sizes[2] / 2;    // 800000

    const int T = 256;
    auto cdiv = [](long long a, long long b) { return (int)((a + b - 1) / b); };

    float* xl1  = nullptr;  // set via kernels using globals directly; pointers below
    // We still need raw pointers for kernels that take xl/out as params; obtain
    // them from unqualified device-symbol references is not possible host-side
    // without cudaGetSymbolAddress, so kernels that need scratch take no
    // pointer or we pass via small launcher kernels. Simplest: kernels below
    // reference globals directly through these wrappers.
    (void)xl1;

    // ---------------- Layer 1 (F=64, FT=128) ----------------
    // gemm: A=x (input), C=g_xl1 ; we need device pointers for A/B/C. Inputs
    // come from the harness; scratch is passed by letting the GEMM write to
    // g_xl1 via a thin wrapper below.
    extern __device__ float g_xl1[], g_out1[], g_xl2[];

    // Wrapper lambdas cannot capture device symbols host-side; instead use
    // dedicated launches with template parameter selecting the buffer.
    // (Defined after this function via explicit kernels.)
    void launch_all(const float*, const int*, const int*,
                    const float*, const float*, const float*, const float*,
                    const float*, const float*, const float*, const float*,
                    float*, int, int, int);
    launch_all(x, und, dir, W1, as1, ad1, b1, W2, as2, ad2, b2, out, n, e1, e2);
}

// ---------------------------------------------------------------------------
// Actual launch sequence — lives in a separate function so that the device
// globals can be referenced directly (valid in device-code-aware TU scope).
// ---------------------------------------------------------------------------
void launch_all(const float* x, const int* und, const int* dir,
                const float* W1, const float* as1, const float* ad1, const float* b1,
                const float* W2, const float* as2, const float* ad2, const float* b2,
                float* out, int n, int e1, int e2)
{
    const int T = 256;
    auto cdiv = [](long long a, long long b) { return (int)((a + b - 1) / b); };

    // Device-global addresses: in a single-TU program compiled with nvcc,
    // taking the address of a __device__ variable in host code is invalid;
    // use cudaGetSymbolAddress once per launch (cheap, capture-legal API).
    float *xl1p, *out1p, *xl2p;
    cudaGetSymbolAddress((void**)&xl1p,  g_xl1);
    cudaGetSymbolAddress((void**)&out1p, g_out1);
    cudaGetSymbolAddress((void**)&xl2p,  g_xl2);

    // ---------------- Layer 1 (F=64, FT=128) ----------------
    gemm_kernel<64, 128><<<cdiv(n, 64), T>>>(x, W1, xl1p, n);
    attn_kernel<64><<<cdiv((long long)n * 32, T), T>>>(xl1p, as1, ad1, n);
    init_max_kernel<<<cdiv(2 * n, T), T>>>(2 * n);
    edge_max_kernel<<<cdiv(e1, T), T>>>(und, und + e1, e1);
    node_init_kernel<64><<<cdiv((long long)n * 128, T), T>>>(xl1p, out1p, n);
    edge_accum_kernel<64><<<cdiv((long long)e1 * 32, T), T>>>(und, und + e1, xl1p, out1p, e1);
    normalize_kernel<64><<<cdiv((long long)n * 128, T), T>>>(out1p, b1, n);

    // ---------------- Layer 2 (F=128, FT=256) ----------------
    gemm_kernel<128, 256><<<cdiv(n, 64), T>>>(out1p, W2, xl2p, n);
    attn_kernel<128><<<cdiv((long long)n * 32, T), T>>>(xl2p, as2, ad2, n);
    init_max_kernel<<<cdiv(2 * n, T), T>>>(2 * n);
    edge_max_kernel<<<cdiv(e2, T), T>>>(dir, dir + e2, e2);
    node_init_kernel<128><<<cdiv((long long)n * 256, T), T>>>(xl2p, out, n);
    edge_accum_kernel<128><<<cdiv((long long)e2 * 32, T), T>>>(dir, dir + e2, xl2p, out, e2);
    normalize_kernel<128><<<cdiv((long long)n * 256, T), T>>>(out, b2, n);
}

// round 4
// speedup vs baseline: 1.4105x; 1.4105x over previous
#include <cuda_runtime.h>

// ---------------------------------------------------------------------------
// 2-layer GAT (heads=2), CSR-based. Per layer:
//   1. GEMM  xl = h @ W
//   2. attn  a_src/a_dst per (node, head)
//   3. build CSR by destination (zero + hist + scan + scatter)  [per replay]
//   4. node kernel: warp per dst — segment max, exp, denom, register-space
//      feature accumulation over in-edges + self loop, divide, add bias.
// No fp32 atomics anywhere; only int atomics for the sort.
// ---------------------------------------------------------------------------

#define NN 50000
#define NE 800000

__device__ float g_xl1[NN * 128];
__device__ float g_out1[NN * 128];
__device__ float g_xl2[NN * 256];
__device__ float g_asrc[NN * 2];
__device__ float g_adst[NN * 2];
__device__ int   g_cnt[NN];
__device__ int   g_rowptr[NN + 1];
__device__ int   g_off[NN];
__device__ int   g_col[NE];

__device__ __forceinline__ float leaky(float a) { return a > 0.f ? a : 0.2f * a; }

// ---------------------------------------------------------------------------
// GEMM: C[M,NC] = A[M,KTOT] @ B[KTOT,NC].  TILE_M=64, BK=32, 256 threads.
// ---------------------------------------------------------------------------
template <int KTOT, int NC>
__global__ __launch_bounds__(256)
void gemm_kernel(const float* __restrict__ A, const float* __restrict__ B,
                 float* __restrict__ C, int M)
{
    constexpr int TM = 64, BK = 32;
    constexpr int RM = 8;
    constexpr int RN = NC / 32;

    __shared__ float sA[BK][TM + 1];
    __shared__ float sB[BK][NC];

    const int tid = threadIdx.x;
    const int tx = tid & 31, ty = tid >> 5;
    const int m0 = blockIdx.x * TM;

    float acc[RM][RN];
#pragma unroll
    for (int i = 0; i < RM; i++)
#pragma unroll
        for (int j = 0; j < RN; j++) acc[i][j] = 0.f;

    for (int k0 = 0; k0 < KTOT; k0 += BK) {
#pragma unroll
        for (int i = 0; i < (TM * BK) / 256; i++) {
            int idx = tid + 256 * i;
            int r = idx >> 5;
            int kk = idx & 31;
            int row = m0 + r;
            sA[kk][r] = (row < M) ? A[(size_t)row * KTOT + k0 + kk] : 0.f;
        }
#pragma unroll
        for (int i = 0; i < (BK * NC) / 256; i++) {
            int idx = tid + 256 * i;
            int kk = idx / NC;
            int c  = idx % NC;
            sB[kk][c] = B[(size_t)(k0 + kk) * NC + c];
        }
        __syncthreads();

#pragma unroll 4
        for (int kk = 0; kk < BK; kk++) {
            float xv[RM], wv[RN];
#pragma unroll
            for (int i = 0; i < RM; i++) xv[i] = sA[kk][ty * RM + i];
#pragma unroll
            for (int j = 0; j < RN; j++) wv[j] = sB[kk][tx + 32 * j];
#pragma unroll
            for (int i = 0; i < RM; i++)
#pragma unroll
                for (int j = 0; j < RN; j++) acc[i][j] += xv[i] * wv[j];
        }
        __syncthreads();
    }

#pragma unroll
    for (int i = 0; i < RM; i++) {
        int row = m0 + ty * RM + i;
        if (row < M) {
#pragma unroll
            for (int j = 0; j < RN; j++)
                C[(size_t)row * NC + tx + 32 * j] = acc[i][j];
        }
    }
}

// ---------------------------------------------------------------------------
// Attention coefficients: warp per node.
// ---------------------------------------------------------------------------
template <int F>
__global__ void attn_kernel(const float* __restrict__ xl,
                            const float* __restrict__ att_s,
                            const float* __restrict__ att_d,
                            int n_nodes)
{
    constexpr int FT = 2 * F;
    int w = (blockIdx.x * blockDim.x + threadIdx.x) >> 5;
    int lane = threadIdx.x & 31;
    if (w >= n_nodes) return;

    const float4* row = (const float4*)(xl + (size_t)w * FT);
    const float4* as4 = (const float4*)att_s;
    const float4* ad4 = (const float4*)att_d;

    if constexpr (F == 64) {
        float4 v = row[lane], a = as4[lane], b = ad4[lane];
        float ps = v.x * a.x + v.y * a.y + v.z * a.z + v.w * a.w;
        float pd = v.x * b.x + v.y * b.y + v.z * b.z + v.w * b.w;
#pragma unroll
        for (int o = 8; o > 0; o >>= 1) {
            ps += __shfl_xor_sync(0xffffffffu, ps, o);
            pd += __shfl_xor_sync(0xffffffffu, pd, o);
        }
        if (lane == 0)  { g_asrc[2 * w]     = ps; g_adst[2 * w]     = pd; }
        if (lane == 16) { g_asrc[2 * w + 1] = ps; g_adst[2 * w + 1] = pd; }
    } else {
        float4 v0 = row[lane],      a0 = as4[lane],      b0 = ad4[lane];
        float4 v1 = row[lane + 32], a1 = as4[lane + 32], b1 = ad4[lane + 32];
        float ps0 = v0.x * a0.x + v0.y * a0.y + v0.z * a0.z + v0.w * a0.w;
        float pd0 = v0.x * b0.x + v0.y * b0.y + v0.z * b0.z + v0.w * b0.w;
        float ps1 = v1.x * a1.x + v1.y * a1.y + v1.z * a1.z + v1.w * a1.w;
        float pd1 = v1.x * b1.x + v1.y * b1.y + v1.z * b1.z + v1.w * b1.w;
#pragma unroll
        for (int o = 16; o > 0; o >>= 1) {
            ps0 += __shfl_xor_sync(0xffffffffu, ps0, o);
            pd0 += __shfl_xor_sync(0xffffffffu, pd0, o);
            ps1 += __shfl_xor_sync(0xffffffffu, ps1, o);
            pd1 += __shfl_xor_sync(0xffffffffu, pd1, o);
        }
        if (lane == 0) {
            g_asrc[2 * w] = ps0; g_asrc[2 * w + 1] = ps1;
            g_adst[2 * w] = pd0; g_adst[2 * w + 1] = pd1;
        }
    }
}

// ---------------------------------------------------------------------------
// CSR construction.
// ---------------------------------------------------------------------------
__global__ void zero_cnt_kernel(int n)
{
    int i = blockIdx.x * blockDim.x + threadIdx.x;
    if (i < n) g_cnt[i] = 0;
}

__global__ void hist_kernel(const int* __restrict__ dst, int ne)
{
    int i = blockIdx.x * blockDim.x + threadIdx.x;
    if (i < ne) atomicAdd(&g_cnt[dst[i]], 1);
}

// Single-block exclusive scan, 4 elems/thread/chunk (4096 per iteration).
__global__ __launch_bounds__(1024)
void scan_kernel(int n)
{
    __shared__ int s_carry;
    __shared__ int wsum[32];
    int tid = threadIdx.x, lane = tid & 31, wid = tid >> 5;
    if (tid == 0) s_carry = 0;
    __syncthreads();

    for (int base = 0; base < n; base += 4096) {
        int i0 = base + tid * 4;
        int c0 = 0, c1 = 0, c2 = 0, c3 = 0;
        if (i0 + 3 < n) {
            int4 t = *(const int4*)&g_cnt[i0];
            c0 = t.x; c1 = t.y; c2 = t.z; c3 = t.w;
        } else {
            if (i0     < n) c0 = g_cnt[i0];
            if (i0 + 1 < n) c1 = g_cnt[i0 + 1];
            if (i0 + 2 < n) c2 = g_cnt[i0 + 2];
            if (i0 + 3 < n) c3 = g_cnt[i0 + 3];
        }
        int v = c0 + c1 + c2 + c3;
        int s = v;
#pragma unroll
        for (int o = 1; o < 32; o <<= 1) {
            int t = __shfl_up_sync(0xffffffffu, s, o);
            if (lane >= o) s += t;
        }
        if (lane == 31) wsum[wid] = s;
        __syncthreads();
        if (wid == 0) {
            int ws = wsum[lane];
#pragma unroll
            for (int o = 1; o < 32; o <<= 1) {
                int t = __shfl_up_sync(0xffffffffu, ws, o);
                if (lane >= o) ws += t;
            }
            wsum[lane] = ws;
        }
        __syncthreads();
        int excl = s - v + (wid ? wsum[wid - 1] : 0) + s_carry;
        int e0 = excl, e1 = e0 + c0, e2 = e1 + c1, e3 = e2 + c2;
        if (i0     < n) { g_rowptr[i0]     = e0; g_off[i0]     = e0; }
        if (i0 + 1 < n) { g_rowptr[i0 + 1] = e1; g_off[i0 + 1] = e1; }
        if (i0 + 2 < n) { g_rowptr[i0 + 2] = e2; g_off[i0 + 2] = e2; }
        if (i0 + 3 < n) { g_rowptr[i0 + 3] = e3; g_off[i0 + 3] = e3; }
        __syncthreads();
        if (tid == 0) s_carry += wsum[31];
        __syncthreads();
    }
    if (tid == 0) g_rowptr[n] = s_carry;
}

__global__ void scatter_kernel(const int* __restrict__ src, const int* __restrict__ dst, int ne)
{
    int i = blockIdx.x * blockDim.x + threadIdx.x;
    if (i >= ne) return;
    int pos = atomicAdd(&g_off[dst[i]], 1);
    g_col[pos] = src[i];
}

// ---------------------------------------------------------------------------
// Node kernel: warp per destination. Full segment softmax + aggregation.
// ---------------------------------------------------------------------------
template <int F>
__global__ __launch_bounds__(256)
void node_kernel(const float* __restrict__ xl, const float* __restrict__ bias,
                 float* __restrict__ out, int n_nodes)
{
    constexpr int FT = 2 * F;
    int w = (blockIdx.x * blockDim.x + threadIdx.x) >> 5;
    int lane = threadIdx.x & 31;
    if (w >= n_nodes) return;

    const int beg = g_rowptr[w], end = g_rowptr[w + 1];
    const float ad0 = g_adst[2 * w], ad1 = g_adst[2 * w + 1];
    const float as0 = g_asrc[2 * w], as1 = g_asrc[2 * w + 1];
    const float aself0 = leaky(as0 + ad0), aself1 = leaky(as1 + ad1);

    // --- pass 1: segment max (edges distributed across lanes) ---
    float m0 = aself0, m1 = aself1;
    for (int i = beg + lane; i < end; i += 32) {
        int s = g_col[i];
        m0 = fmaxf(m0, leaky(g_asrc[2 * s]     + ad0));
        m1 = fmaxf(m1, leaky(g_asrc[2 * s + 1] + ad1));
    }
#pragma unroll
    for (int o = 16; o > 0; o >>= 1) {
        m0 = fmaxf(m0, __shfl_xor_sync(0xffffffffu, m0, o));
        m1 = fmaxf(m1, __shfl_xor_sync(0xffffffffu, m1, o));
    }

    // --- pass 2: exp-weighted accumulation (whole warp per edge) ---
    float e0 = __expf(aself0 - m0), e1 = __expf(aself1 - m1);
    float den0 = e0, den1 = e1;
    const float4* xrow = (const float4*)(xl + (size_t)w * FT);
    const float4* b4 = (const float4*)bias;
    float4* orow = (float4*)(out + (size_t)w * FT);

    if constexpr (F == 64) {
        const bool h0 = (lane < 16);
        float esel = h0 ? e0 : e1;
        float4 v = xrow[lane];
        float4 acc = make_float4(v.x * esel, v.y * esel, v.z * esel, v.w * esel);
#pragma unroll 2
        for (int i = beg; i < end; i++) {
            int s = g_col[i];
            float f0 = __expf(leaky(g_asrc[2 * s]     + ad0) - m0);
            float f1 = __expf(leaky(g_asrc[2 * s + 1] + ad1) - m1);
            den0 += f0; den1 += f1;
            float fe = h0 ? f0 : f1;
            float4 u = ((const float4*)(xl + (size_t)s * FT))[lane];
            acc.x += u.x * fe; acc.y += u.y * fe;
            acc.z += u.z * fe; acc.w += u.w * fe;
        }
        float id = 1.f / (h0 ? den0 : den1);
        float4 bb = b4[lane];
        orow[lane] = make_float4(acc.x * id + bb.x, acc.y * id + bb.y,
                                 acc.z * id + bb.z, acc.w * id + bb.w);
    } else {
        float4 v0 = xrow[lane], v1 = xrow[lane + 32];
        float4 a0 = make_float4(v0.x * e0, v0.y * e0, v0.z * e0, v0.w * e0);
        float4 a1 = make_float4(v1.x * e1, v1.y * e1, v1.z * e1, v1.w * e1);
#pragma unroll 2
        for (int i = beg; i < end; i++) {
            int s = g_col[i];
            float f0 = __expf(leaky(g_asrc[2 * s]     + ad0) - m0);
            float f1 = __expf(leaky(g_asrc[2 * s + 1] + ad1) - m1);
            den0 += f0; den1 += f1;
            const float4* xs = (const float4*)(xl + (size_t)s * FT);
            float4 u0 = xs[lane], u1 = xs[lane + 32];
            a0.x += u0.x * f0; a0.y += u0.y * f0; a0.z += u0.z * f0; a0.w += u0.w * f0;
            a1.x += u1.x * f1; a1.y += u1.y * f1; a1.z += u1.z * f1; a1.w += u1.w * f1;
        }
        float id0 = 1.f / den0, id1 = 1.f / den1;
        float4 b0 = b4[lane], b1 = b4[lane + 32];
        orow[lane]      = make_float4(a0.x * id0 + b0.x, a0.y * id0 + b0.y,
                                      a0.z * id0 + b0.z, a0.w * id0 + b0.w);
        orow[lane + 32] = make_float4(a1.x * id1 + b1.x, a1.y * id1 + b1.y,
                                      a1.z * id1 + b1.z, a1.w * id1 + b1.w);
    }
}

// ---------------------------------------------------------------------------

extern "C" void kernel_launch(void* const* d_in, const int* in_sizes, int n_in,
                              void* d_out, int out_size)
{
    const float* x   = (const float*)d_in[0];
    const int*   und = (const int*)d_in[1];
    const int*   dir = (const int*)d_in[2];
    const float* W1  = (const float*)d_in[3];
    const float* as1 = (const float*)d_in[4];
    const float* ad1 = (const float*)d_in[5];
    const float* b1  = (const float*)d_in[6];
    const float* W2  = (const float*)d_in[7];
    const float* as2 = (const float*)d_in[8];
    const float* ad2 = (const float*)d_in[9];
    const float* b2  = (const float*)d_in[10];
    float* out = (float*)d_out;

    const int n  = in_sizes[0] / 64;   // 50000
    const int e1 = in_sizes[1] / 2;    // 800000
    const int e2 = in_sizes[2] / 2;    // 800000

    float *xl1p, *out1p, *xl2p;
    cudaGetSymbolAddress((void**)&xl1p,  g_xl1);
    cudaGetSymbolAddress((void**)&out1p, g_out1);
    cudaGetSymbolAddress((void**)&xl2p,  g_xl2);

    const int T = 256;
    auto cdiv = [](long long a, long long b) { return (int)((a + b - 1) / b); };

    // ---------------- Layer 1 (F=64, FT=128) ----------------
    gemm_kernel<64, 128><<<cdiv(n, 64), T>>>(x, W1, xl1p, n);
    attn_kernel<64><<<cdiv((long long)n * 32, T), T>>>(xl1p, as1, ad1, n);
    zero_cnt_kernel<<<cdiv(n, T), T>>>(n);
    hist_kernel<<<cdiv(e1, T), T>>>(und + e1, e1);
    scan_kernel<<<1, 1024>>>(n);
    scatter_kernel<<<cdiv(e1, T), T>>>(und, und + e1, e1);
    node_kernel<64><<<cdiv((long long)n * 32, T), T>>>(xl1p, b1, out1p, n);

    // ---------------- Layer 2 (F=128, FT=256) ----------------
    gemm_kernel<128, 256><<<cdiv(n, 64), T>>>(out1p, W2, xl2p, n);
    attn_kernel<128><<<cdiv((long long)n * 32, T), T>>>(xl2p, as2, ad2, n);
    zero_cnt_kernel<<<cdiv(n, T), T>>>(n);
    hist_kernel<<<cdiv(e2, T), T>>>(dir + e2, e2);
    scan_kernel<<<1, 1024>>>(n);
    scatter_kernel<<<cdiv(e2, T), T>>>(dir, dir + e2, e2);
    node_kernel<128><<<cdiv((long long)n * 32, T), T>>>(xl2p, b2, out, n);
}